// round 5
// baseline (speedup 1.0000x reference)
#include <cuda_runtime.h>
#include <cuda_bf16.h>

// ---------------- problem constants ----------------
#define BB 16
#define SS 512
#define HH 768
#define TT 2
#define NN 32
#define LL 64
#define EE 8
#define DD 128
#define AA 128
#define INV_SQRT_D 0.08838834764831845f

// ---------------- scratch (static device globals; no allocs allowed) ----------
__device__ float g_efea[BB*TT*EE*HH];        // [B,T,E,H]
__device__ float g_feas[BB*TT*HH];           // [B,T,H]
__device__ float g_q[BB*TT*EE*DD];           // [B,T,E,D]
__device__ float g_k[BB*TT*NN*LL*DD];        // [B,T,N,L,D]  33.5 MB
__device__ float g_msgs[BB*TT*NN*EE*HH];     // [B,T,N,E,H]  25 MB
__device__ float g_pooled[BB*TT*NN*HH];      // [B,T,N,H]
__device__ float g_wf[BB*TT*AA];             // [B,T,A]
__device__ float g_wp[BB*TT*NN*AA];          // [B,T,N,A]
__device__ float g_score[BB*TT*NN];          // [B,T,N]
__device__ float g_x[BB*SS*HH];              // [B,S,H]  25 MB
__device__ float g_q2[BB*SS*DD];
__device__ float g_k2[BB*SS*DD];
__device__ float g_v2[BB*SS*HH];             // 25 MB
__device__ float g_s2[BB*SS*SS];             // 16.8 MB

// ---------------- generic tiled SGEMM: C = A[M,K] @ B[K,N] (+bias) ----------
// 64x64 tile, K-step 16, 256 threads, 4x4 microtile. Strided-batched via z.
__global__ void sgemm_bias(const float* __restrict__ A, const float* __restrict__ Bw,
                           const float* __restrict__ bias, float* __restrict__ C,
                           int M, int N, int K,
                           long long sA, long long sB, long long sC)
{
    A += (long long)blockIdx.z * sA;
    Bw += (long long)blockIdx.z * sB;
    C += (long long)blockIdx.z * sC;

    __shared__ float As[16][65];
    __shared__ float Bs[16][65];

    int tid = threadIdx.x;
    int tx = tid & 15, ty = tid >> 4;
    int row0 = blockIdx.y * 64;
    int col0 = blockIdx.x * 64;

    float acc[4][4] = {};

    for (int k0 = 0; k0 < K; k0 += 16) {
#pragma unroll
        for (int i = 0; i < 4; i++) {
            int idx = tid + i * 256;
            int m = idx >> 4, kk = idx & 15;
            float v = 0.f;
            int gr = row0 + m;
            if (gr < M) v = A[(long long)gr * K + (k0 + kk)];
            As[kk][m] = v;
        }
#pragma unroll
        for (int i = 0; i < 4; i++) {
            int idx = tid + i * 256;
            int kk = idx >> 6, n = idx & 63;
            float v = 0.f;
            int gc = col0 + n;
            if (gc < N) v = Bw[(long long)(k0 + kk) * N + gc];
            Bs[kk][n] = v;
        }
        __syncthreads();
#pragma unroll
        for (int kk = 0; kk < 16; kk++) {
            float a[4], b[4];
#pragma unroll
            for (int i = 0; i < 4; i++) a[i] = As[kk][ty * 4 + i];
#pragma unroll
            for (int j = 0; j < 4; j++) b[j] = Bs[kk][tx * 4 + j];
#pragma unroll
            for (int i = 0; i < 4; i++)
#pragma unroll
                for (int j = 0; j < 4; j++)
                    acc[i][j] += a[i] * b[j];
        }
        __syncthreads();
    }

#pragma unroll
    for (int i = 0; i < 4; i++) {
        int r = row0 + ty * 4 + i;
        if (r >= M) continue;
#pragma unroll
        for (int j = 0; j < 4; j++) {
            int c = col0 + tx * 4 + j;
            if (c >= N) continue;
            float v = acc[i][j];
            if (bias) v += bias[c];
            C[(long long)r * N + c] = v;
        }
    }
}

// ---------------- NT SGEMM: C = alpha * A[M,K] @ B[N,K]^T  (batched) --------
__global__ void sgemm_nt(const float* __restrict__ A, const float* __restrict__ Bm,
                         float* __restrict__ C,
                         int M, int N, int K, float alpha,
                         long long sA, long long sB, long long sC)
{
    A += (long long)blockIdx.z * sA;
    Bm += (long long)blockIdx.z * sB;
    C += (long long)blockIdx.z * sC;

    __shared__ float As[16][65];
    __shared__ float Bs[16][65];

    int tid = threadIdx.x;
    int tx = tid & 15, ty = tid >> 4;
    int row0 = blockIdx.y * 64;
    int col0 = blockIdx.x * 64;

    float acc[4][4] = {};

    for (int k0 = 0; k0 < K; k0 += 16) {
#pragma unroll
        for (int i = 0; i < 4; i++) {
            int idx = tid + i * 256;
            int m = idx >> 4, kk = idx & 15;
            float v = 0.f;
            int gr = row0 + m;
            if (gr < M) v = A[(long long)gr * K + (k0 + kk)];
            As[kk][m] = v;
        }
#pragma unroll
        for (int i = 0; i < 4; i++) {
            int idx = tid + i * 256;
            int n = idx >> 4, kk = idx & 15;
            float v = 0.f;
            int gc = col0 + n;
            if (gc < N) v = Bm[(long long)gc * K + (k0 + kk)];
            Bs[kk][n] = v;
        }
        __syncthreads();
#pragma unroll
        for (int kk = 0; kk < 16; kk++) {
            float a[4], b[4];
#pragma unroll
            for (int i = 0; i < 4; i++) a[i] = As[kk][ty * 4 + i];
#pragma unroll
            for (int j = 0; j < 4; j++) b[j] = Bs[kk][tx * 4 + j];
#pragma unroll
            for (int i = 0; i < 4; i++)
#pragma unroll
                for (int j = 0; j < 4; j++)
                    acc[i][j] += a[i] * b[j];
        }
        __syncthreads();
    }

#pragma unroll
    for (int i = 0; i < 4; i++) {
        int r = row0 + ty * 4 + i;
        if (r >= M) continue;
#pragma unroll
        for (int j = 0; j < 4; j++) {
            int c = col0 + tx * 4 + j;
            if (c >= N) continue;
            C[(long long)r * N + c] = alpha * acc[i][j];
        }
    }
}

// ---------------- gather entity spans + per-entity mean ----------------------
__global__ void gather_kernel(const float* __restrict__ xs, const int* __restrict__ spans,
                              float* __restrict__ efea, float* __restrict__ feas)
{
    int bt = blockIdx.x;            // B*T
    int b = bt / TT;
    int pos = spans[bt];
    for (int h = threadIdx.x; h < HH; h += blockDim.x) {
        float s = 0.f;
#pragma unroll
        for (int e = 0; e < EE; e++) {
            float v = xs[((long long)b * SS + pos + e) * HH + h];
            efea[((long long)bt * EE + e) * HH + h] = v;
            s += v;
        }
        feas[(long long)bt * HH + h] = s * (1.f / EE);
    }
}

// ---------------- fused per-neighbor SDPA: logits+softmax+msgs+pool ----------
__global__ void sdpa_kernel(const float* __restrict__ q,    // [B,T,E,D]
                            const float* __restrict__ k,    // [B,T,N,L,D]
                            const float* __restrict__ neigh,// [B,T,N,L,H]
                            float* __restrict__ msgs,       // [B,T,N,E,H]
                            float* __restrict__ pooled)     // [B,T,N,H]
{
    int btn = blockIdx.x;           // B*T*N
    int bt = btn / NN;

    __shared__ float sq[EE * DD];          // 4 KB
    __shared__ float sk[LL * 129];         // 33 KB, padded stride to kill conflicts
    __shared__ float sl[EE][LL];           // logits -> attn

    int tid = threadIdx.x;                 // 256

    for (int i = tid; i < EE * DD; i += 256)
        sq[i] = q[(long long)bt * EE * DD + i];
    {
        const float* kb = k + (long long)btn * LL * DD;
        for (int i = tid; i < LL * DD; i += 256) {
            int l = i / DD, d = i % DD;
            sk[l * 129 + d] = kb[i];
        }
    }
    __syncthreads();

    // logits [E,L]
    for (int idx = tid; idx < EE * LL; idx += 256) {
        int e = idx / LL, l = idx % LL;
        float s = 0.f;
        const float* qp = sq + e * DD;
        const float* kp = sk + l * 129;
#pragma unroll 8
        for (int d = 0; d < DD; d++) s += qp[d] * kp[d];
        sl[e][l] = s * INV_SQRT_D;
    }
    __syncthreads();

    // per-row softmax over L=64 (warp w handles row e=w)
    int w = tid >> 5, lane = tid & 31;
    if (w < EE) {
        float v0 = sl[w][lane], v1 = sl[w][lane + 32];
        float m = fmaxf(v0, v1);
#pragma unroll
        for (int off = 16; off > 0; off >>= 1)
            m = fmaxf(m, __shfl_xor_sync(0xffffffff, m, off));
        float e0 = __expf(v0 - m), e1 = __expf(v1 - m);
        float s = e0 + e1;
#pragma unroll
        for (int off = 16; off > 0; off >>= 1)
            s += __shfl_xor_sync(0xffffffff, s, off);
        float inv = 1.f / s;
        sl[w][lane] = e0 * inv;
        sl[w][lane + 32] = e1 * inv;
    }
    __syncthreads();

    // msgs = attn @ neigh, one pass over neigh; pool on the fly
    const float* nb = neigh + (long long)btn * LL * HH;
    for (int h = tid; h < HH; h += 256) {
        float acc[EE] = {};
        for (int l = 0; l < LL; l++) {
            float v = nb[(long long)l * HH + h];
#pragma unroll
            for (int e = 0; e < EE; e++) acc[e] += sl[e][l] * v;
        }
        float p = 0.f;
#pragma unroll
        for (int e = 0; e < EE; e++) {
            msgs[((long long)btn * EE + e) * HH + h] = acc[e];
            p += acc[e];
        }
        pooled[(long long)btn * HH + h] = p * (1.f / EE);
    }
}

// ---------------- attn-attr score: leaky(cat@Wa+ba) + d*wb+bb -> sigmoid ----
__global__ void score_kernel(const float* __restrict__ wf, const float* __restrict__ wp,
                             const float* __restrict__ Wa, const float* __restrict__ ba,
                             const float* __restrict__ dists, const float* __restrict__ wb,
                             const float* __restrict__ bb, float* __restrict__ score)
{
    int btn = blockIdx.x;            // B*T*N
    int bt = btn / NN;
    int tid = threadIdx.x;           // 256 == 2*A
    float t;
    if (tid < AA) t = wf[(long long)bt * AA + tid] * Wa[tid];
    else          t = wp[(long long)btn * AA + (tid - AA)] * Wa[tid];

    __shared__ float red[256];
    red[tid] = t;
    __syncthreads();
    for (int s = 128; s > 0; s >>= 1) {
        if (tid < s) red[tid] += red[tid + s];
        __syncthreads();
    }
    if (tid == 0) {
        float xv = red[0] + ba[0];
        xv = (xv > 0.f) ? xv : 0.01f * xv;   // leaky_relu slope 0.01
        xv += dists[btn] * wb[0] + bb[0];
        score[btn] = 1.f / (1.f + __expf(-xv));
    }
}

// ---------------- scatter-add gated messages into entity spans --------------
__global__ void scatter_kernel(const float* __restrict__ score,
                               const float* __restrict__ msgs,
                               const int* __restrict__ spans,
                               float* __restrict__ x)
{
    int bte = blockIdx.x;            // B*T*E
    int e = bte % EE;
    int bt = bte / EE;
    int b = bt / TT;
    int pos = spans[bt] + e;

    __shared__ float sc[NN];
    if (threadIdx.x < NN) sc[threadIdx.x] = score[(long long)bt * NN + threadIdx.x];
    __syncthreads();

    for (int h = threadIdx.x; h < HH; h += blockDim.x) {
        float d = 0.f;
        for (int n = 0; n < NN; n++)
            d += sc[n] * msgs[(((long long)bt * NN + n) * EE + e) * HH + h];
        atomicAdd(&x[((long long)b * SS + pos) * HH + h], d);
    }
}

// ---------------- row softmax over 512 cols ---------------------------------
__global__ void softmax512(float* __restrict__ X)
{
    long long row = blockIdx.x;
    float* p = X + row * SS;
    int tid = threadIdx.x;           // 256
    float v0 = p[tid], v1 = p[tid + 256];

    __shared__ float red[256];
    red[tid] = fmaxf(v0, v1);
    __syncthreads();
    for (int s = 128; s > 0; s >>= 1) {
        if (tid < s) red[tid] = fmaxf(red[tid], red[tid + s]);
        __syncthreads();
    }
    float m = red[0];
    __syncthreads();

    float e0 = __expf(v0 - m), e1 = __expf(v1 - m);
    red[tid] = e0 + e1;
    __syncthreads();
    for (int s = 128; s > 0; s >>= 1) {
        if (tid < s) red[tid] += red[tid + s];
        __syncthreads();
    }
    float inv = 1.f / red[0];
    p[tid] = e0 * inv;
    p[tid + 256] = e1 * inv;
}

// ---------------- host orchestration ----------------------------------------
static void launch_sgemm(const float* A, const float* Bw, const float* bias, float* C,
                         int M, int N, int K, int batch,
                         long long sA, long long sB, long long sC)
{
    dim3 g((N + 63) / 64, (M + 63) / 64, batch);
    sgemm_bias<<<g, 256>>>(A, Bw, bias, C, M, N, K, sA, sB, sC);
}

extern "C" void kernel_launch(void* const* d_in, const int* in_sizes, int n_in,
                              void* d_out, int out_size)
{
    const float* xs    = (const float*)d_in[0];
    const float* neigh = (const float*)d_in[1];
    const float* dists = (const float*)d_in[2];
    const int*   spans = (const int*)d_in[3];
    const float* Wq = (const float*)d_in[4];
    const float* bq = (const float*)d_in[5];
    const float* Wk = (const float*)d_in[6];
    const float* bk = (const float*)d_in[7];
    const float* Wv = (const float*)d_in[8];
    const float* bv = (const float*)d_in[9];
    const float* Ww = (const float*)d_in[10];
    const float* bw = (const float*)d_in[11];
    const float* Wa = (const float*)d_in[12];
    const float* ba = (const float*)d_in[13];
    const float* wb = (const float*)d_in[14];
    const float* bb = (const float*)d_in[15];
    float* out = (float*)d_out;

    float *p_efea, *p_feas, *p_q, *p_k, *p_msgs, *p_pooled, *p_wf, *p_wp, *p_score;
    float *p_x, *p_q2, *p_k2, *p_v2, *p_s2;
    cudaGetSymbolAddress((void**)&p_efea,   g_efea);
    cudaGetSymbolAddress((void**)&p_feas,   g_feas);
    cudaGetSymbolAddress((void**)&p_q,      g_q);
    cudaGetSymbolAddress((void**)&p_k,      g_k);
    cudaGetSymbolAddress((void**)&p_msgs,   g_msgs);
    cudaGetSymbolAddress((void**)&p_pooled, g_pooled);
    cudaGetSymbolAddress((void**)&p_wf,     g_wf);
    cudaGetSymbolAddress((void**)&p_wp,     g_wp);
    cudaGetSymbolAddress((void**)&p_score,  g_score);
    cudaGetSymbolAddress((void**)&p_x,      g_x);
    cudaGetSymbolAddress((void**)&p_q2,     g_q2);
    cudaGetSymbolAddress((void**)&p_k2,     g_k2);
    cudaGetSymbolAddress((void**)&p_v2,     g_v2);
    cudaGetSymbolAddress((void**)&p_s2,     g_s2);

    // 1) gather spans + feas
    gather_kernel<<<BB * TT, 256>>>(xs, spans, p_efea, p_feas);

    // 2) q = e_fea @ Wq + bq  [256,768]x[768,128]
    launch_sgemm(p_efea, Wq, bq, p_q, BB * TT * EE, DD, HH, 1, 0, 0, 0);

    // 3) k = neigh @ Wk + bk  [65536,768]x[768,128]  (dominant GEMM #1)
    launch_sgemm(neigh, Wk, bk, p_k, BB * TT * NN * LL, DD, HH, 1, 0, 0, 0);

    // 4) per-neighbor SDPA -> msgs, pooled
    sdpa_kernel<<<BB * TT * NN, 256>>>(p_q, p_k, neigh, p_msgs, p_pooled);

    // 5) wf = feas @ Ww + bw ; wp = pooled @ Ww + bw
    launch_sgemm(p_feas, Ww, bw, p_wf, BB * TT, AA, HH, 1, 0, 0, 0);
    launch_sgemm(p_pooled, Ww, bw, p_wp, BB * TT * NN, AA, HH, 1, 0, 0, 0);

    // 6) sigmoid attn-attr score
    score_kernel<<<BB * TT * NN, 256>>>(p_wf, p_wp, Wa, ba, dists, wb, bb, p_score);

    // 7) x = xs ; x[spans] += sum_n score*msgs  (atomic: spans may overlap across T)
    cudaMemcpyAsync(p_x, xs, (size_t)BB * SS * HH * sizeof(float),
                    cudaMemcpyDeviceToDevice, 0);
    scatter_kernel<<<BB * TT * EE, 256>>>(p_score, p_msgs, spans, p_x);

    // 8) q2/k2/v2 projections
    launch_sgemm(p_x, Wq, bq, p_q2, BB * SS, DD, HH, 1, 0, 0, 0);
    launch_sgemm(p_x, Wk, bk, p_k2, BB * SS, DD, HH, 1, 0, 0, 0);
    launch_sgemm(p_x, Wv, bv, p_v2, BB * SS, HH, HH, 1, 0, 0, 0);

    // 9) s2 = q2 @ k2^T * inv_sqrt_d  (batched NT, per-b 512x512x128)
    {
        dim3 g(SS / 64, SS / 64, BB);
        sgemm_nt<<<g, 256>>>(p_q2, p_k2, p_s2, SS, SS, DD, INV_SQRT_D,
                             (long long)SS * DD, (long long)SS * DD,
                             (long long)SS * SS);
    }

    // 10) softmax rows
    softmax512<<<BB * SS, 256>>>(p_s2);

    // 11) out = P @ v2  (batched 512x768x512)
    launch_sgemm(p_s2, p_v2, nullptr, out, SS, HH, SS, BB,
                 (long long)SS * SS, (long long)SS * HH, (long long)SS * HH);
}

// round 10
// speedup vs baseline: 1.8221x; 1.8221x over previous
#include <cuda_runtime.h>
#include <cuda_bf16.h>
#include <cstdint>

// ---------------- problem constants ----------------
#define BB 16
#define SS 512
#define HH 768
#define TT 2
#define NN 32
#define LL 64
#define EE 8
#define DD 128
#define AA 128
#define INV_SQRT_D 0.08838834764831845f

__device__ __forceinline__ uint32_t smem_to_u32(const void* p) {
    uint32_t a;
    asm("{ .reg .u64 t; cvta.to.shared.u64 t, %1; cvt.u32.u64 %0, t; }"
        : "=r"(a) : "l"(p));
    return a;
}
__device__ __forceinline__ uint32_t lds32(uint32_t a) {
    uint32_t v; asm volatile("ld.shared.b32 %0, [%1];" : "=r"(v) : "r"(a)); return v;
}
__device__ __forceinline__ void cp16(uint32_t s, const void* g) {
    asm volatile("cp.async.cg.shared.global [%0], [%1], 16;" :: "r"(s), "l"(g));
}
__device__ __forceinline__ void mma16816(float* d, const uint32_t* a, const uint32_t* b) {
    asm volatile(
        "mma.sync.aligned.m16n8k16.row.col.f32.bf16.bf16.f32 "
        "{%0,%1,%2,%3}, {%4,%5,%6,%7}, {%8,%9}, {%0,%1,%2,%3};"
        : "+f"(d[0]), "+f"(d[1]), "+f"(d[2]), "+f"(d[3])
        : "r"(a[0]), "r"(a[1]), "r"(a[2]), "r"(a[3]), "r"(b[0]), "r"(b[1]));
}

// ---------------- scratch (static device globals; no allocs allowed) ----------
__device__ float g_efea[BB*TT*EE*HH];
__device__ float g_feas[BB*TT*HH];
__device__ float g_q[BB*TT*EE*DD];
__device__ float g_k[BB*TT*NN*LL*DD];
__device__ float g_msgs[BB*TT*NN*EE*HH];
__device__ float g_pooled[BB*TT*NN*HH];
__device__ float g_wf[BB*TT*AA];
__device__ float g_wp[BB*TT*NN*AA];
__device__ float g_score[BB*TT*NN];
__device__ float g_x[BB*SS*HH];
__device__ float g_q2[BB*SS*DD];
__device__ float g_k2[BB*SS*DD];
__device__ float g_v2[BB*SS*HH];
__device__ float g_s2[BB*SS*SS];

// bf16 hi/lo split operands (aligned for uint4/cp.async access)
__device__ __align__(256) __nv_bfloat16 g_nh_h[BB*TT*NN*LL*HH];
__device__ __align__(256) __nv_bfloat16 g_nh_l[BB*TT*NN*LL*HH];
__device__ __align__(256) __nv_bfloat16 g_xh[BB*SS*HH];
__device__ __align__(256) __nv_bfloat16 g_xl[BB*SS*HH];
__device__ __align__(256) __nv_bfloat16 g_q2h[BB*SS*DD];
__device__ __align__(256) __nv_bfloat16 g_q2l[BB*SS*DD];
__device__ __align__(256) __nv_bfloat16 g_k2h[BB*SS*DD];
__device__ __align__(256) __nv_bfloat16 g_k2l[BB*SS*DD];
__device__ __align__(256) __nv_bfloat16 g_Ph[BB*SS*SS];
__device__ __align__(256) __nv_bfloat16 g_Pl[BB*SS*SS];
__device__ __align__(256) __nv_bfloat16 g_vth[BB*HH*SS];
__device__ __align__(256) __nv_bfloat16 g_vtl[BB*HH*SS];
__device__ __align__(256) __nv_bfloat16 g_WkTh[DD*HH];
__device__ __align__(256) __nv_bfloat16 g_WkTl[DD*HH];
__device__ __align__(256) __nv_bfloat16 g_WqTh[DD*HH];
__device__ __align__(256) __nv_bfloat16 g_WqTl[DD*HH];
__device__ __align__(256) __nv_bfloat16 g_WvTh[HH*HH];
__device__ __align__(256) __nv_bfloat16 g_WvTl[HH*HH];

// ================= mma.sync bf16x3 GEMM: C[M,N] = alpha*(A @ B^T) + bias =====
// A hi/lo [M,K] row-major, B hi/lo [N,K] row-major (K-major both).
// Requires M%128==0, N%128==0, K%32==0 (true for every call site).
// Block 128x128, 8 warps (warp tile 32x64), K-step 32, cp.async double buffer.
#define MM_LDA 40                        // padded K-stride (bf16) -> conflict-free LDS
#define MM_TILE_B (128*MM_LDA*2)         // 10240 B per tile
#define MM_STAGE_B (4*MM_TILE_B)         // Ah|Al|Bh|Bl = 40960 B
#define MM_SMEM_BYTES (2*MM_STAGE_B)     // 81920 B

__global__ void __launch_bounds__(256)
mmgemm(const __nv_bfloat16* __restrict__ Ah, const __nv_bfloat16* __restrict__ Al,
       const __nv_bfloat16* __restrict__ Bh, const __nv_bfloat16* __restrict__ Bl,
       const float* __restrict__ bias, float* __restrict__ C,
       int M, int N, int K, float alpha,
       long long sA, long long sB, long long sC)
{
    extern __shared__ char smem[];
    const uint32_t s0 = smem_to_u32(smem);

    Ah += (long long)blockIdx.z * sA;  Al += (long long)blockIdx.z * sA;
    Bh += (long long)blockIdx.z * sB;  Bl += (long long)blockIdx.z * sB;
    C  += (long long)blockIdx.z * sC;

    const int tid = threadIdx.x;
    const int row0 = blockIdx.y * 128, col0 = blockIdx.x * 128;

    const int lr = tid >> 2, lseg = tid & 3;       // loader: 64 rows x 4 segs, x2 halves

    auto load_stage = [&](int stage, int k0) {
        uint32_t sb = s0 + stage * MM_STAGE_B;
#pragma unroll
        for (int half = 0; half < 2; half++) {
            int row = lr + half * 64;
            uint32_t so = (uint32_t)(row * MM_LDA + lseg * 8) * 2;
            long long ga = (long long)(row0 + row) * K + k0 + lseg * 8;
            long long gb = (long long)(col0 + row) * K + k0 + lseg * 8;
            cp16(sb + so,                 Ah + ga);
            cp16(sb + MM_TILE_B + so,     Al + ga);
            cp16(sb + 2 * MM_TILE_B + so, Bh + gb);
            cp16(sb + 3 * MM_TILE_B + so, Bl + gb);
        }
        asm volatile("cp.async.commit_group;");
    };

    const int lane = tid & 31, wid = tid >> 5;
    const int g = lane >> 2, tg = lane & 3;
    const int wm = (wid & 3) * 32, wn = (wid >> 2) * 64;

    float acc[2][8][4];
#pragma unroll
    for (int mt = 0; mt < 2; mt++)
#pragma unroll
        for (int nt = 0; nt < 8; nt++)
#pragma unroll
            for (int i = 0; i < 4; i++) acc[mt][nt][i] = 0.f;

    const int KB = K / 32;
    load_stage(0, 0);

    for (int kb = 0; kb < KB; kb++) {
        if (kb + 1 < KB) {
            load_stage((kb + 1) & 1, (kb + 1) * 32);
            asm volatile("cp.async.wait_group 1;");
        } else {
            asm volatile("cp.async.wait_group 0;");
        }
        __syncthreads();

        const uint32_t sb = s0 + (kb & 1) * MM_STAGE_B;
#pragma unroll
        for (int kk = 0; kk < 32; kk += 16) {
            // preload B fragments for this k16 (hi & lo)
            uint32_t bh[8][2], bl[8][2];
#pragma unroll
            for (int nt = 0; nt < 8; nt++) {
                uint32_t bo = sb + 2 * MM_TILE_B +
                              (uint32_t)((wn + nt * 8 + g) * MM_LDA + kk + tg * 2) * 2;
                bh[nt][0] = lds32(bo);              bh[nt][1] = lds32(bo + 16);
                bl[nt][0] = lds32(bo + MM_TILE_B);  bl[nt][1] = lds32(bo + MM_TILE_B + 16);
            }
#pragma unroll
            for (int mt = 0; mt < 2; mt++) {
                uint32_t ao = sb + (uint32_t)((wm + mt * 16 + g) * MM_LDA + kk + tg * 2) * 2;
                uint32_t ah[4], al[4];
                ah[0] = lds32(ao);
                ah[1] = lds32(ao + 8 * MM_LDA * 2);
                ah[2] = lds32(ao + 16);
                ah[3] = lds32(ao + 8 * MM_LDA * 2 + 16);
                al[0] = lds32(ao + MM_TILE_B);
                al[1] = lds32(ao + MM_TILE_B + 8 * MM_LDA * 2);
                al[2] = lds32(ao + MM_TILE_B + 16);
                al[3] = lds32(ao + MM_TILE_B + 8 * MM_LDA * 2 + 16);
#pragma unroll
                for (int nt = 0; nt < 8; nt++) {
                    mma16816(acc[mt][nt], ah, bh[nt]);   // Ah*Bh
                    mma16816(acc[mt][nt], ah, bl[nt]);   // Ah*Bl
                    mma16816(acc[mt][nt], al, bh[nt]);   // Al*Bh
                }
            }
        }
        __syncthreads();
    }

    // epilogue: alpha + bias, float2 stores (cols are even -> 8B aligned)
#pragma unroll
    for (int mt = 0; mt < 2; mt++) {
        const int r = row0 + wm + mt * 16 + g;
#pragma unroll
        for (int nt = 0; nt < 8; nt++) {
            const int c = col0 + wn + nt * 8 + tg * 2;
            float b0 = 0.f, b1 = 0.f;
            if (bias) { b0 = bias[c]; b1 = bias[c + 1]; }
            float2 v0 = make_float2(acc[mt][nt][0] * alpha + b0,
                                    acc[mt][nt][1] * alpha + b1);
            float2 v1 = make_float2(acc[mt][nt][2] * alpha + b0,
                                    acc[mt][nt][3] * alpha + b1);
            *(float2*)(C + (long long)r * N + c) = v0;
            *(float2*)(C + (long long)(r + 8) * N + c) = v1;
        }
    }
}

// ---------------- fp32 -> bf16 hi/lo split (vectorized) ---------------------
__global__ void split4(const float4* __restrict__ in, __nv_bfloat162* __restrict__ hi,
                       __nv_bfloat162* __restrict__ lo, long long n4)
{
    long long i = (long long)blockIdx.x * blockDim.x + threadIdx.x;
    long long stride = (long long)gridDim.x * blockDim.x;
    for (; i < n4; i += stride) {
        float4 v = in[i];
        __nv_bfloat162 h0, h1, l0, l1;
        h0.x = __float2bfloat16(v.x); h0.y = __float2bfloat16(v.y);
        h1.x = __float2bfloat16(v.z); h1.y = __float2bfloat16(v.w);
        l0.x = __float2bfloat16(v.x - __bfloat162float(h0.x));
        l0.y = __float2bfloat16(v.y - __bfloat162float(h0.y));
        l1.x = __float2bfloat16(v.z - __bfloat162float(h1.x));
        l1.y = __float2bfloat16(v.w - __bfloat162float(h1.y));
        hi[2*i] = h0; hi[2*i+1] = h1;
        lo[2*i] = l0; lo[2*i+1] = l1;
    }
}

// ---------------- fp32 [R,C] -> transposed bf16 hi/lo [C,R] (batched) -------
__global__ void transpose_split(const float* __restrict__ in,
                                __nv_bfloat16* __restrict__ oh,
                                __nv_bfloat16* __restrict__ ol,
                                int R, int C, long long sIn, long long sOut)
{
    in += (long long)blockIdx.z * sIn;
    oh += (long long)blockIdx.z * sOut;
    ol += (long long)blockIdx.z * sOut;
    __shared__ float t[32][33];
    int c0 = blockIdx.x * 32, r0 = blockIdx.y * 32;
    for (int i = threadIdx.y; i < 32; i += 8) {
        int r = r0 + i, c = c0 + threadIdx.x;
        t[i][threadIdx.x] = (r < R && c < C) ? in[(long long)r * C + c] : 0.f;
    }
    __syncthreads();
    for (int i = threadIdx.y; i < 32; i += 8) {
        int c = c0 + i, r = r0 + threadIdx.x;
        if (c < C && r < R) {
            float v = t[threadIdx.x][i];
            __nv_bfloat16 h = __float2bfloat16(v);
            oh[(long long)c * R + r] = h;
            ol[(long long)c * R + r] = __float2bfloat16(v - __bfloat162float(h));
        }
    }
}

// ---------------- fp32 tiled SGEMM (kept for small GEMMs) -------------------
__global__ void sgemm_bias(const float* __restrict__ A, const float* __restrict__ Bw,
                           const float* __restrict__ bias, float* __restrict__ C,
                           int M, int N, int K,
                           long long sA, long long sB, long long sC)
{
    A += (long long)blockIdx.z * sA;
    Bw += (long long)blockIdx.z * sB;
    C += (long long)blockIdx.z * sC;

    __shared__ float As[16][65];
    __shared__ float Bs[16][65];

    int tid = threadIdx.x;
    int tx = tid & 15, ty = tid >> 4;
    int row0 = blockIdx.y * 64;
    int col0 = blockIdx.x * 64;

    float acc[4][4] = {};

    for (int k0 = 0; k0 < K; k0 += 16) {
#pragma unroll
        for (int i = 0; i < 4; i++) {
            int idx = tid + i * 256;
            int m = idx >> 4, kk = idx & 15;
            float v = 0.f;
            int gr = row0 + m;
            if (gr < M) v = A[(long long)gr * K + (k0 + kk)];
            As[kk][m] = v;
        }
#pragma unroll
        for (int i = 0; i < 4; i++) {
            int idx = tid + i * 256;
            int kk = idx >> 6, n = idx & 63;
            float v = 0.f;
            int gc = col0 + n;
            if (gc < N) v = Bw[(long long)(k0 + kk) * N + gc];
            Bs[kk][n] = v;
        }
        __syncthreads();
#pragma unroll
        for (int kk = 0; kk < 16; kk++) {
            float a[4], b[4];
#pragma unroll
            for (int i = 0; i < 4; i++) a[i] = As[kk][ty * 4 + i];
#pragma unroll
            for (int j = 0; j < 4; j++) b[j] = Bs[kk][tx * 4 + j];
#pragma unroll
            for (int i = 0; i < 4; i++)
#pragma unroll
                for (int j = 0; j < 4; j++)
                    acc[i][j] += a[i] * b[j];
        }
        __syncthreads();
    }

#pragma unroll
    for (int i = 0; i < 4; i++) {
        int r = row0 + ty * 4 + i;
        if (r >= M) continue;
#pragma unroll
        for (int j = 0; j < 4; j++) {
            int c = col0 + tx * 4 + j;
            if (c >= N) continue;
            float v = acc[i][j];
            if (bias) v += bias[c];
            C[(long long)r * N + c] = v;
        }
    }
}

// ---------------- gather entity spans + per-entity mean ----------------------
__global__ void gather_kernel(const float* __restrict__ xs, const int* __restrict__ spans,
                              float* __restrict__ efea, float* __restrict__ feas)
{
    int bt = blockIdx.x;
    int b = bt / TT;
    int pos = spans[bt];
    for (int h = threadIdx.x; h < HH; h += blockDim.x) {
        float s = 0.f;
#pragma unroll
        for (int e = 0; e < EE; e++) {
            float v = xs[((long long)b * SS + pos + e) * HH + h];
            efea[((long long)bt * EE + e) * HH + h] = v;
            s += v;
        }
        feas[(long long)bt * HH + h] = s * (1.f / EE);
    }
}

// ---------------- fused per-neighbor SDPA: logits+softmax+msgs+pool ----------
__global__ void sdpa_kernel(const float* __restrict__ q,
                            const float* __restrict__ k,
                            const float* __restrict__ neigh,
                            float* __restrict__ msgs,
                            float* __restrict__ pooled)
{
    int btn = blockIdx.x;
    int bt = btn / NN;

    __shared__ float sq[EE * DD];
    __shared__ float sk[LL * 129];
    __shared__ float sl[EE][LL];

    int tid = threadIdx.x;

    for (int i = tid; i < EE * DD; i += 256)
        sq[i] = q[(long long)bt * EE * DD + i];
    {
        const float* kb = k + (long long)btn * LL * DD;
        for (int i = tid; i < LL * DD; i += 256) {
            int l = i / DD, d = i % DD;
            sk[l * 129 + d] = kb[i];
        }
    }
    __syncthreads();

    for (int idx = tid; idx < EE * LL; idx += 256) {
        int e = idx / LL, l = idx % LL;
        float s = 0.f;
        const float* qp = sq + e * DD;
        const float* kp = sk + l * 129;
#pragma unroll 8
        for (int d = 0; d < DD; d++) s += qp[d] * kp[d];
        sl[e][l] = s * INV_SQRT_D;
    }
    __syncthreads();

    int w = tid >> 5, lane = tid & 31;
    if (w < EE) {
        float v0 = sl[w][lane], v1 = sl[w][lane + 32];
        float m = fmaxf(v0, v1);
#pragma unroll
        for (int off = 16; off > 0; off >>= 1)
            m = fmaxf(m, __shfl_xor_sync(0xffffffff, m, off));
        float e0 = __expf(v0 - m), e1 = __expf(v1 - m);
        float s = e0 + e1;
#pragma unroll
        for (int off = 16; off > 0; off >>= 1)
            s += __shfl_xor_sync(0xffffffff, s, off);
        float inv = 1.f / s;
        sl[w][lane] = e0 * inv;
        sl[w][lane + 32] = e1 * inv;
    }
    __syncthreads();

    const float* nb = neigh + (long long)btn * LL * HH;
    for (int h = tid; h < HH; h += 256) {
        float acc[EE] = {};
        for (int l = 0; l < LL; l++) {
            float v = nb[(long long)l * HH + h];
#pragma unroll
            for (int e = 0; e < EE; e++) acc[e] += sl[e][l] * v;
        }
        float p = 0.f;
#pragma unroll
        for (int e = 0; e < EE; e++) {
            msgs[((long long)btn * EE + e) * HH + h] = acc[e];
            p += acc[e];
        }
        pooled[(long long)btn * HH + h] = p * (1.f / EE);
    }
}

// ---------------- attn-attr score -------------------------------------------
__global__ void score_kernel(const float* __restrict__ wf, const float* __restrict__ wp,
                             const float* __restrict__ Wa, const float* __restrict__ ba,
                             const float* __restrict__ dists, const float* __restrict__ wb,
                             const float* __restrict__ bb, float* __restrict__ score)
{
    int btn = blockIdx.x;
    int bt = btn / NN;
    int tid = threadIdx.x;
    float t;
    if (tid < AA) t = wf[(long long)bt * AA + tid] * Wa[tid];
    else          t = wp[(long long)btn * AA + (tid - AA)] * Wa[tid];

    __shared__ float red[256];
    red[tid] = t;
    __syncthreads();
    for (int s = 128; s > 0; s >>= 1) {
        if (tid < s) red[tid] += red[tid + s];
        __syncthreads();
    }
    if (tid == 0) {
        float xv = red[0] + ba[0];
        xv = (xv > 0.f) ? xv : 0.01f * xv;
        xv += dists[btn] * wb[0] + bb[0];
        score[btn] = 1.f / (1.f + __expf(-xv));
    }
}

// ---------------- scatter-add gated messages into entity spans --------------
__global__ void scatter_kernel(const float* __restrict__ score,
                               const float* __restrict__ msgs,
                               const int* __restrict__ spans,
                               float* __restrict__ x)
{
    int bte = blockIdx.x;
    int e = bte % EE;
    int bt = bte / EE;
    int b = bt / TT;
    int pos = spans[bt] + e;

    __shared__ float sc[NN];
    if (threadIdx.x < NN) sc[threadIdx.x] = score[(long long)bt * NN + threadIdx.x];
    __syncthreads();

    for (int h = threadIdx.x; h < HH; h += blockDim.x) {
        float d = 0.f;
        for (int n = 0; n < NN; n++)
            d += sc[n] * msgs[(((long long)bt * NN + n) * EE + e) * HH + h];
        atomicAdd(&x[((long long)b * SS + pos) * HH + h], d);
    }
}

// ---------------- row softmax over 512 cols ---------------------------------
__global__ void softmax512(float* __restrict__ X)
{
    long long row = blockIdx.x;
    float* p = X + row * SS;
    int tid = threadIdx.x;
    float v0 = p[tid], v1 = p[tid + 256];

    __shared__ float red[256];
    red[tid] = fmaxf(v0, v1);
    __syncthreads();
    for (int s = 128; s > 0; s >>= 1) {
        if (tid < s) red[tid] = fmaxf(red[tid], red[tid + s]);
        __syncthreads();
    }
    float m = red[0];
    __syncthreads();

    float e0 = __expf(v0 - m), e1 = __expf(v1 - m);
    red[tid] = e0 + e1;
    __syncthreads();
    for (int s = 128; s > 0; s >>= 1) {
        if (tid < s) red[tid] += red[tid + s];
        __syncthreads();
    }
    float inv = 1.f / red[0];
    p[tid] = e0 * inv;
    p[tid + 256] = e1 * inv;
}

// ---------------- host orchestration ----------------------------------------
static void launch_sgemm(const float* A, const float* Bw, const float* bias, float* C,
                         int M, int N, int K)
{
    dim3 g((N + 63) / 64, (M + 63) / 64, 1);
    sgemm_bias<<<g, 256>>>(A, Bw, bias, C, M, N, K, 0, 0, 0);
}

static void launch_mm(const __nv_bfloat16* Ah, const __nv_bfloat16* Al,
                      const __nv_bfloat16* Bh, const __nv_bfloat16* Bl,
                      const float* bias, float* C,
                      int M, int N, int K, float alpha, int batch,
                      long long sA, long long sB, long long sC)
{
    dim3 g(N / 128, M / 128, batch);
    mmgemm<<<g, 256, MM_SMEM_BYTES>>>(Ah, Al, Bh, Bl, bias, C, M, N, K, alpha, sA, sB, sC);
}

static void launch_split(const float* in, __nv_bfloat16* hi, __nv_bfloat16* lo, long long n)
{
    long long n4 = n / 4;
    int blocks = (int)((n4 + 255) / 256);
    if (blocks > 8192) blocks = 8192;
    split4<<<blocks, 256>>>((const float4*)in, (__nv_bfloat162*)hi, (__nv_bfloat162*)lo, n4);
}

extern "C" void kernel_launch(void* const* d_in, const int* in_sizes, int n_in,
                              void* d_out, int out_size)
{
    const float* xs    = (const float*)d_in[0];
    const float* neigh = (const float*)d_in[1];
    const float* dists = (const float*)d_in[2];
    const int*   spans = (const int*)d_in[3];
    const float* Wq = (const float*)d_in[4];
    const float* bq = (const float*)d_in[5];
    const float* Wk = (const float*)d_in[6];
    const float* bk = (const float*)d_in[7];
    const float* Wv = (const float*)d_in[8];
    const float* bv = (const float*)d_in[9];
    const float* Ww = (const float*)d_in[10];
    const float* bw = (const float*)d_in[11];
    const float* Wa = (const float*)d_in[12];
    const float* ba = (const float*)d_in[13];
    const float* wb = (const float*)d_in[14];
    const float* bb = (const float*)d_in[15];
    float* out = (float*)d_out;

    cudaFuncSetAttribute(mmgemm, cudaFuncAttributeMaxDynamicSharedMemorySize, MM_SMEM_BYTES);

    float *p_efea, *p_feas, *p_q, *p_k, *p_msgs, *p_pooled, *p_wf, *p_wp, *p_score;
    float *p_x, *p_q2, *p_k2, *p_v2, *p_s2;
    cudaGetSymbolAddress((void**)&p_efea,   g_efea);
    cudaGetSymbolAddress((void**)&p_feas,   g_feas);
    cudaGetSymbolAddress((void**)&p_q,      g_q);
    cudaGetSymbolAddress((void**)&p_k,      g_k);
    cudaGetSymbolAddress((void**)&p_msgs,   g_msgs);
    cudaGetSymbolAddress((void**)&p_pooled, g_pooled);
    cudaGetSymbolAddress((void**)&p_wf,     g_wf);
    cudaGetSymbolAddress((void**)&p_wp,     g_wp);
    cudaGetSymbolAddress((void**)&p_score,  g_score);
    cudaGetSymbolAddress((void**)&p_x,      g_x);
    cudaGetSymbolAddress((void**)&p_q2,     g_q2);
    cudaGetSymbolAddress((void**)&p_k2,     g_k2);
    cudaGetSymbolAddress((void**)&p_v2,     g_v2);
    cudaGetSymbolAddress((void**)&p_s2,     g_s2);

    __nv_bfloat16 *nh_h, *nh_l, *xh, *xl, *q2h, *q2l, *k2h, *k2l, *Ph, *Pl, *vth, *vtl;
    __nv_bfloat16 *WkTh, *WkTl, *WqTh, *WqTl, *WvTh, *WvTl;
    cudaGetSymbolAddress((void**)&nh_h, g_nh_h);
    cudaGetSymbolAddress((void**)&nh_l, g_nh_l);
    cudaGetSymbolAddress((void**)&xh,   g_xh);
    cudaGetSymbolAddress((void**)&xl,   g_xl);
    cudaGetSymbolAddress((void**)&q2h,  g_q2h);
    cudaGetSymbolAddress((void**)&q2l,  g_q2l);
    cudaGetSymbolAddress((void**)&k2h,  g_k2h);
    cudaGetSymbolAddress((void**)&k2l,  g_k2l);
    cudaGetSymbolAddress((void**)&Ph,   g_Ph);
    cudaGetSymbolAddress((void**)&Pl,   g_Pl);
    cudaGetSymbolAddress((void**)&vth,  g_vth);
    cudaGetSymbolAddress((void**)&vtl,  g_vtl);
    cudaGetSymbolAddress((void**)&WkTh, g_WkTh);
    cudaGetSymbolAddress((void**)&WkTl, g_WkTl);
    cudaGetSymbolAddress((void**)&WqTh, g_WqTh);
    cudaGetSymbolAddress((void**)&WqTl, g_WqTl);
    cudaGetSymbolAddress((void**)&WvTh, g_WvTh);
    cudaGetSymbolAddress((void**)&WvTl, g_WvTl);

    // --- weight transposes+splits (tiny): W[H,N] -> W^T[N,H] hi/lo ---
    {
        dim3 g8(32, 8);
        transpose_split<<<dim3(DD / 32, HH / 32, 1), g8>>>(Wk, WkTh, WkTl, HH, DD, 0, 0);
        transpose_split<<<dim3(DD / 32, HH / 32, 1), g8>>>(Wq, WqTh, WqTl, HH, DD, 0, 0);
        transpose_split<<<dim3(HH / 32, HH / 32, 1), g8>>>(Wv, WvTh, WvTl, HH, HH, 0, 0);
    }

    // 1) gather spans + feas
    gather_kernel<<<BB * TT, 256>>>(xs, spans, p_efea, p_feas);

    // 2) q = e_fea @ Wq + bq  (small, fp32)
    launch_sgemm(p_efea, Wq, bq, p_q, BB * TT * EE, DD, HH);

    // 3) k = neigh @ Wk + bk  via mma.sync bf16x3  (M=65536, N=128, K=768)
    launch_split(neigh, nh_h, nh_l, (long long)BB * TT * NN * LL * HH);
    launch_mm(nh_h, nh_l, WkTh, WkTl, bk, p_k,
              BB * TT * NN * LL, DD, HH, 1.f, 1, 0, 0, 0);

    // 4) per-neighbor SDPA -> msgs, pooled
    sdpa_kernel<<<BB * TT * NN, 256>>>(p_q, p_k, neigh, p_msgs, p_pooled);

    // 5) wf, wp (small/medium, fp32)
    launch_sgemm(p_feas, Ww, bw, p_wf, BB * TT, AA, HH);
    launch_sgemm(p_pooled, Ww, bw, p_wp, BB * TT * NN, AA, HH);

    // 6) sigmoid attn-attr score
    score_kernel<<<BB * TT * NN, 256>>>(p_wf, p_wp, Wa, ba, dists, wb, bb, p_score);

    // 7) x = xs ; x[spans] += sum_n score*msgs
    cudaMemcpyAsync(p_x, xs, (size_t)BB * SS * HH * sizeof(float),
                    cudaMemcpyDeviceToDevice, 0);
    scatter_kernel<<<BB * TT * EE, 256>>>(p_score, p_msgs, spans, p_x);

    // 8) q2/k2/v2 projections via mma.sync
    launch_split(p_x, xh, xl, (long long)BB * SS * HH);
    launch_mm(xh, xl, WqTh, WqTl, bq, p_q2, BB * SS, DD, HH, 1.f, 1, 0, 0, 0);
    launch_mm(xh, xl, WkTh, WkTl, bk, p_k2, BB * SS, DD, HH, 1.f, 1, 0, 0, 0);
    launch_mm(xh, xl, WvTh, WvTl, bv, p_v2, BB * SS, HH, HH, 1.f, 1, 0, 0, 0);

    // 9) s2 = q2 @ k2^T * inv_sqrt_d  (batched 512x512x128; both K-major)
    launch_split(p_q2, q2h, q2l, (long long)BB * SS * DD);
    launch_split(p_k2, k2h, k2l, (long long)BB * SS * DD);
    launch_mm(q2h, q2l, k2h, k2l, nullptr, p_s2, SS, SS, DD, INV_SQRT_D, BB,
              (long long)SS * DD, (long long)SS * DD, (long long)SS * SS);

    // 10) softmax rows, then split P
    softmax512<<<BB * SS, 256>>>(p_s2);
    launch_split(p_s2, Ph, Pl, (long long)BB * SS * SS);

    // 11) out = P @ v2  (v2^T as [H,S] K-major B operand; batched 512x768x512)
    transpose_split<<<dim3(HH / 32, SS / 32, BB), dim3(32, 8)>>>(
        p_v2, vth, vtl, SS, HH, (long long)SS * HH, (long long)HH * SS);
    launch_mm(Ph, Pl, vth, vtl, nullptr, out, SS, HH, SS, 1.f, BB,
              (long long)SS * SS, (long long)HH * SS, (long long)SS * HH);
}

// round 15
// speedup vs baseline: 1.8396x; 1.0096x over previous
#include <cuda_runtime.h>
#include <cuda_bf16.h>
#include <cstdint>

// ---------------- problem constants ----------------
#define BB 16
#define SS 512
#define HH 768
#define TT 2
#define NN 32
#define LL 64
#define EE 8
#define DD 128
#define AA 128
#define INV_SQRT_D 0.08838834764831845f

__device__ __forceinline__ uint32_t smem_to_u32(const void* p) {
    uint32_t a;
    asm("{ .reg .u64 t; cvta.to.shared.u64 t, %1; cvt.u32.u64 %0, t; }"
        : "=r"(a) : "l"(p));
    return a;
}
__device__ __forceinline__ void cp16(uint32_t s, const void* g) {
    asm volatile("cp.async.cg.shared.global [%0], [%1], 16;" :: "r"(s), "l"(g));
}
__device__ __forceinline__ void ldsm4(uint32_t* r, uint32_t addr) {
    asm volatile("ldmatrix.sync.aligned.m8n8.x4.shared.b16 {%0,%1,%2,%3}, [%4];"
                 : "=r"(r[0]), "=r"(r[1]), "=r"(r[2]), "=r"(r[3]) : "r"(addr));
}
__device__ __forceinline__ void mma16816(float* d, const uint32_t* a, const uint32_t* b) {
    asm volatile(
        "mma.sync.aligned.m16n8k16.row.col.f32.bf16.bf16.f32 "
        "{%0,%1,%2,%3}, {%4,%5,%6,%7}, {%8,%9}, {%0,%1,%2,%3};"
        : "+f"(d[0]), "+f"(d[1]), "+f"(d[2]), "+f"(d[3])
        : "r"(a[0]), "r"(a[1]), "r"(a[2]), "r"(a[3]), "r"(b[0]), "r"(b[1]));
}

// ---------------- scratch (static device globals; no allocs allowed) ----------
__device__ float g_efea[BB*TT*EE*HH];
__device__ float g_feas[BB*TT*HH];
__device__ float g_q[BB*TT*EE*DD];
__device__ float g_k[BB*TT*NN*LL*DD];
__device__ float g_msgs[BB*TT*NN*EE*HH];
__device__ float g_pooled[BB*TT*NN*HH];
__device__ float g_wf[BB*TT*AA];
__device__ float g_wp[BB*TT*NN*AA];
__device__ float g_score[BB*TT*NN];
__device__ float g_x[BB*SS*HH];
__device__ float g_q2[BB*SS*DD];
__device__ float g_k2[BB*SS*DD];
__device__ float g_v2[BB*SS*HH];
__device__ float g_s2[BB*SS*SS];

// bf16 hi/lo B-side operands
__device__ __align__(256) __nv_bfloat16 g_k2h[BB*SS*DD];
__device__ __align__(256) __nv_bfloat16 g_k2l[BB*SS*DD];
__device__ __align__(256) __nv_bfloat16 g_vth[BB*HH*SS];
__device__ __align__(256) __nv_bfloat16 g_vtl[BB*HH*SS];
__device__ __align__(256) __nv_bfloat16 g_WkTh[DD*HH];
__device__ __align__(256) __nv_bfloat16 g_WkTl[DD*HH];
__device__ __align__(256) __nv_bfloat16 g_WqTh[DD*HH];
__device__ __align__(256) __nv_bfloat16 g_WqTl[DD*HH];
__device__ __align__(256) __nv_bfloat16 g_WvTh[HH*HH];
__device__ __align__(256) __nv_bfloat16 g_WvTl[HH*HH];

// ======== fused-split mma.sync GEMM: C[M,N] = alpha*(A_f32 @ B^T) + bias =====
// A fp32 [M,K] row-major (converted to bf16 hi/lo in-kernel).
// B hi/lo bf16 [N,K] row-major. M,N % 128 == 0, K % 32 == 0 at every call site.
// Block 128x128, 8 warps (32x64 warp tiles), K-step 32, cp.async double buffer,
// ldmatrix fragment loads, 3-term split accumulate (AhBh + AhBl + AlBh).
#define MM_LDA 40                          // padded bf16 K-stride -> conflict-free
#define MM_TILE_B (128*MM_LDA*2)           // 10240 B per bf16 tile
#define MM_STAGE_B (4*MM_TILE_B)           // Ah|Al|Bh|Bl = 40960 B
#define MM_F32_STRIDE 36                   // padded fp32 row stride (floats)
#define MM_F32_TILE (128*MM_F32_STRIDE*4)  // 18432 B
#define MM_SMEM_BYTES (2*MM_STAGE_B + 2*MM_F32_TILE)   // 118784 B

__global__ void __launch_bounds__(256)
mmf(const float* __restrict__ Af,
    const __nv_bfloat16* __restrict__ Bh, const __nv_bfloat16* __restrict__ Bl,
    const float* __restrict__ bias, float* __restrict__ C,
    int M, int N, int K, float alpha,
    long long sA, long long sB, long long sC)
{
    extern __shared__ char smem[];
    const uint32_t s0 = smem_to_u32(smem);

    Af += (long long)blockIdx.z * sA;
    Bh += (long long)blockIdx.z * sB;  Bl += (long long)blockIdx.z * sB;
    C  += (long long)blockIdx.z * sC;

    const int tid = threadIdx.x;
    const int row0 = blockIdx.y * 128, col0 = blockIdx.x * 128;
    const int lane = tid & 31, wid = tid >> 5;
    const int wm = (wid & 3) * 32, wn = (wid >> 2) * 64;

    auto load_stage = [&](int stage, int k0) {
        uint32_t sb = s0 + stage * MM_STAGE_B;
        uint32_t sf = s0 + 2 * MM_STAGE_B + stage * MM_F32_TILE;
        // B hi/lo bf16: 128 rows x 32 k (64B/row), 4 segs
        {
            int r = tid >> 2, sg = tid & 3;
#pragma unroll
            for (int half = 0; half < 2; half++) {
                int row = r + half * 64;
                uint32_t so = (uint32_t)(row * MM_LDA + sg * 8) * 2;
                long long gb = (long long)(col0 + row) * K + k0 + sg * 8;
                cp16(sb + 2 * MM_TILE_B + so, Bh + gb);
                cp16(sb + 3 * MM_TILE_B + so, Bl + gb);
            }
        }
        // A fp32: 128 rows x 32 k (128B/row), 8 segs
        {
            int r = tid >> 3, sg = tid & 7;
#pragma unroll
            for (int i = 0; i < 4; i++) {
                int row = r + i * 32;
                uint32_t so = (uint32_t)(row * MM_F32_STRIDE + sg * 4) * 4;
                long long ga = (long long)(row0 + row) * K + k0 + sg * 4;
                cp16(sf + so, Af + ga);
            }
        }
        asm volatile("cp.async.commit_group;");
    };

    float acc[2][8][4];
#pragma unroll
    for (int mt = 0; mt < 2; mt++)
#pragma unroll
        for (int nt = 0; nt < 8; nt++)
#pragma unroll
            for (int i = 0; i < 4; i++) acc[mt][nt][i] = 0.f;

    const int KB = K / 32;
    load_stage(0, 0);

    for (int kb = 0; kb < KB; kb++) {
        if (kb + 1 < KB) {
            load_stage((kb + 1) & 1, (kb + 1) * 32);
            asm volatile("cp.async.wait_group 1;");
        } else {
            asm volatile("cp.async.wait_group 0;");
        }
        __syncthreads();

        // convert fp32 A stage -> bf16 hi/lo tiles (same stage)
        {
            uint32_t sf = s0 + 2 * MM_STAGE_B + (kb & 1) * MM_F32_TILE;
            uint32_t sb = s0 + (kb & 1) * MM_STAGE_B;
            int row = tid >> 1, h = tid & 1;
#pragma unroll
            for (int j = 0; j < 4; j++) {
                float4 v;
                uint32_t a = sf + (uint32_t)(row * MM_F32_STRIDE + h * 16 + j * 4) * 4;
                asm volatile("ld.shared.v4.f32 {%0,%1,%2,%3}, [%4];"
                             : "=f"(v.x), "=f"(v.y), "=f"(v.z), "=f"(v.w) : "r"(a));
                __nv_bfloat162 h0, h1, l0, l1;
                h0.x = __float2bfloat16(v.x); h0.y = __float2bfloat16(v.y);
                h1.x = __float2bfloat16(v.z); h1.y = __float2bfloat16(v.w);
                l0.x = __float2bfloat16(v.x - __bfloat162float(h0.x));
                l0.y = __float2bfloat16(v.y - __bfloat162float(h0.y));
                l1.x = __float2bfloat16(v.z - __bfloat162float(h1.x));
                l1.y = __float2bfloat16(v.w - __bfloat162float(h1.y));
                uint32_t hw0 = *(uint32_t*)&h0, hw1 = *(uint32_t*)&h1;
                uint32_t lw0 = *(uint32_t*)&l0, lw1 = *(uint32_t*)&l1;
                uint32_t da = sb + (uint32_t)(row * MM_LDA + h * 16 + j * 4) * 2;
                asm volatile("st.shared.v2.b32 [%0], {%1,%2};"
                             :: "r"(da), "r"(hw0), "r"(hw1));
                asm volatile("st.shared.v2.b32 [%0], {%1,%2};"
                             :: "r"(da + MM_TILE_B), "r"(lw0), "r"(lw1));
            }
        }
        __syncthreads();

        const uint32_t sb = s0 + (kb & 1) * MM_STAGE_B;
#pragma unroll
        for (int kk = 0; kk < 32; kk += 16) {
            uint32_t bh[8][2], bl[8][2];
#pragma unroll
            for (int p = 0; p < 4; p++) {
                int tilei = lane >> 3;
                int nrow = wn + (2 * p + (tilei >> 1)) * 8 + (lane & 7);
                int koff = kk + (tilei & 1) * 8;
                uint32_t ba = sb + 2 * MM_TILE_B + (uint32_t)(nrow * MM_LDA + koff) * 2;
                uint32_t t[4];
                ldsm4(t, ba);
                bh[2*p][0] = t[0]; bh[2*p][1] = t[1];
                bh[2*p+1][0] = t[2]; bh[2*p+1][1] = t[3];
                ldsm4(t, ba + MM_TILE_B);
                bl[2*p][0] = t[0]; bl[2*p][1] = t[1];
                bl[2*p+1][0] = t[2]; bl[2*p+1][1] = t[3];
            }
#pragma unroll
            for (int mt = 0; mt < 2; mt++) {
                int arow = wm + mt * 16 + ((lane >> 3) & 1) * 8 + (lane & 7);
                int akoff = kk + (lane >> 4) * 8;
                uint32_t aa = sb + (uint32_t)(arow * MM_LDA + akoff) * 2;
                uint32_t ah[4], al[4];
                ldsm4(ah, aa);
                ldsm4(al, aa + MM_TILE_B);
#pragma unroll
                for (int nt = 0; nt < 8; nt++) {
                    mma16816(acc[mt][nt], ah, bh[nt]);   // Ah*Bh
                    mma16816(acc[mt][nt], ah, bl[nt]);   // Ah*Bl
                    mma16816(acc[mt][nt], al, bh[nt]);   // Al*Bh
                }
            }
        }
        __syncthreads();
    }

    const int g = lane >> 2, tg = lane & 3;
#pragma unroll
    for (int mt = 0; mt < 2; mt++) {
        const int r = row0 + wm + mt * 16 + g;
#pragma unroll
        for (int nt = 0; nt < 8; nt++) {
            const int c = col0 + wn + nt * 8 + tg * 2;
            float b0 = 0.f, b1 = 0.f;
            if (bias) { b0 = bias[c]; b1 = bias[c + 1]; }
            float2 v0 = make_float2(acc[mt][nt][0] * alpha + b0,
                                    acc[mt][nt][1] * alpha + b1);
            float2 v1 = make_float2(acc[mt][nt][2] * alpha + b0,
                                    acc[mt][nt][3] * alpha + b1);
            *(float2*)(C + (long long)r * N + c) = v0;
            *(float2*)(C + (long long)(r + 8) * N + c) = v1;
        }
    }
}

// ---------------- fp32 -> bf16 hi/lo split (k2 only; tiny) -------------------
__global__ void split4(const float4* __restrict__ in, __nv_bfloat162* __restrict__ hi,
                       __nv_bfloat162* __restrict__ lo, long long n4)
{
    long long i = (long long)blockIdx.x * blockDim.x + threadIdx.x;
    long long stride = (long long)gridDim.x * blockDim.x;
    for (; i < n4; i += stride) {
        float4 v = in[i];
        __nv_bfloat162 h0, h1, l0, l1;
        h0.x = __float2bfloat16(v.x); h0.y = __float2bfloat16(v.y);
        h1.x = __float2bfloat16(v.z); h1.y = __float2bfloat16(v.w);
        l0.x = __float2bfloat16(v.x - __bfloat162float(h0.x));
        l0.y = __float2bfloat16(v.y - __bfloat162float(h0.y));
        l1.x = __float2bfloat16(v.z - __bfloat162float(h1.x));
        l1.y = __float2bfloat16(v.w - __bfloat162float(h1.y));
        hi[2*i] = h0; hi[2*i+1] = h1;
        lo[2*i] = l0; lo[2*i+1] = l1;
    }
}

// ---------------- fp32 [R,C] -> transposed bf16 hi/lo [C,R] (batched) -------
__global__ void transpose_split(const float* __restrict__ in,
                                __nv_bfloat16* __restrict__ oh,
                                __nv_bfloat16* __restrict__ ol,
                                int R, int C, long long sIn, long long sOut)
{
    in += (long long)blockIdx.z * sIn;
    oh += (long long)blockIdx.z * sOut;
    ol += (long long)blockIdx.z * sOut;
    __shared__ float t[32][33];
    int c0 = blockIdx.x * 32, r0 = blockIdx.y * 32;
    for (int i = threadIdx.y; i < 32; i += 8) {
        int r = r0 + i, c = c0 + threadIdx.x;
        t[i][threadIdx.x] = (r < R && c < C) ? in[(long long)r * C + c] : 0.f;
    }
    __syncthreads();
    for (int i = threadIdx.y; i < 32; i += 8) {
        int c = c0 + i, r = r0 + threadIdx.x;
        if (c < C && r < R) {
            float v = t[threadIdx.x][i];
            __nv_bfloat16 h = __float2bfloat16(v);
            oh[(long long)c * R + r] = h;
            ol[(long long)c * R + r] = __float2bfloat16(v - __bfloat162float(h));
        }
    }
}

// ---------------- fp32 tiled SGEMM (small GEMMs) ----------------------------
__global__ void sgemm_bias(const float* __restrict__ A, const float* __restrict__ Bw,
                           const float* __restrict__ bias, float* __restrict__ C,
                           int M, int N, int K,
                           long long sA, long long sB, long long sC)
{
    A += (long long)blockIdx.z * sA;
    Bw += (long long)blockIdx.z * sB;
    C += (long long)blockIdx.z * sC;

    __shared__ float As[16][65];
    __shared__ float Bs[16][65];

    int tid = threadIdx.x;
    int tx = tid & 15, ty = tid >> 4;
    int row0 = blockIdx.y * 64;
    int col0 = blockIdx.x * 64;

    float acc[4][4] = {};

    for (int k0 = 0; k0 < K; k0 += 16) {
#pragma unroll
        for (int i = 0; i < 4; i++) {
            int idx = tid + i * 256;
            int m = idx >> 4, kk = idx & 15;
            float v = 0.f;
            int gr = row0 + m;
            if (gr < M) v = A[(long long)gr * K + (k0 + kk)];
            As[kk][m] = v;
        }
#pragma unroll
        for (int i = 0; i < 4; i++) {
            int idx = tid + i * 256;
            int kk = idx >> 6, n = idx & 63;
            float v = 0.f;
            int gc = col0 + n;
            if (gc < N) v = Bw[(long long)(k0 + kk) * N + gc];
            Bs[kk][n] = v;
        }
        __syncthreads();
#pragma unroll
        for (int kk = 0; kk < 16; kk++) {
            float a[4], b[4];
#pragma unroll
            for (int i = 0; i < 4; i++) a[i] = As[kk][ty * 4 + i];
#pragma unroll
            for (int j = 0; j < 4; j++) b[j] = Bs[kk][tx * 4 + j];
#pragma unroll
            for (int i = 0; i < 4; i++)
#pragma unroll
                for (int j = 0; j < 4; j++)
                    acc[i][j] += a[i] * b[j];
        }
        __syncthreads();
    }

#pragma unroll
    for (int i = 0; i < 4; i++) {
        int r = row0 + ty * 4 + i;
        if (r >= M) continue;
#pragma unroll
        for (int j = 0; j < 4; j++) {
            int c = col0 + tx * 4 + j;
            if (c >= N) continue;
            float v = acc[i][j];
            if (bias) v += bias[c];
            C[(long long)r * N + c] = v;
        }
    }
}

// ---------------- gather entity spans + per-entity mean ----------------------
__global__ void gather_kernel(const float* __restrict__ xs, const int* __restrict__ spans,
                              float* __restrict__ efea, float* __restrict__ feas)
{
    int bt = blockIdx.x;
    int b = bt / TT;
    int pos = spans[bt];
    for (int h = threadIdx.x; h < HH; h += blockDim.x) {
        float s = 0.f;
#pragma unroll
        for (int e = 0; e < EE; e++) {
            float v = xs[((long long)b * SS + pos + e) * HH + h];
            efea[((long long)bt * EE + e) * HH + h] = v;
            s += v;
        }
        feas[(long long)bt * HH + h] = s * (1.f / EE);
    }
}

// ---------------- fused per-neighbor SDPA: logits+softmax+msgs+pool ----------
__global__ void sdpa_kernel(const float* __restrict__ q,
                            const float* __restrict__ k,
                            const float* __restrict__ neigh,
                            float* __restrict__ msgs,
                            float* __restrict__ pooled)
{
    int btn = blockIdx.x;
    int bt = btn / NN;

    __shared__ float sq[EE * DD];
    __shared__ float sk[LL * 129];
    __shared__ float sl[EE][LL];

    int tid = threadIdx.x;

    for (int i = tid; i < EE * DD; i += 256)
        sq[i] = q[(long long)bt * EE * DD + i];
    {
        const float* kb = k + (long long)btn * LL * DD;
        for (int i = tid; i < LL * DD; i += 256) {
            int l = i / DD, d = i % DD;
            sk[l * 129 + d] = kb[i];
        }
    }
    __syncthreads();

    for (int idx = tid; idx < EE * LL; idx += 256) {
        int e = idx / LL, l = idx % LL;
        float s = 0.f;
        const float* qp = sq + e * DD;
        const float* kp = sk + l * 129;
#pragma unroll 8
        for (int d = 0; d < DD; d++) s += qp[d] * kp[d];
        sl[e][l] = s * INV_SQRT_D;
    }
    __syncthreads();

    int w = tid >> 5, lane = tid & 31;
    if (w < EE) {
        float v0 = sl[w][lane], v1 = sl[w][lane + 32];
        float m = fmaxf(v0, v1);
#pragma unroll
        for (int off = 16; off > 0; off >>= 1)
            m = fmaxf(m, __shfl_xor_sync(0xffffffff, m, off));
        float e0 = __expf(v0 - m), e1 = __expf(v1 - m);
        float s = e0 + e1;
#pragma unroll
        for (int off = 16; off > 0; off >>= 1)
            s += __shfl_xor_sync(0xffffffff, s, off);
        float inv = 1.f / s;
        sl[w][lane] = e0 * inv;
        sl[w][lane + 32] = e1 * inv;
    }
    __syncthreads();

    const float* nb = neigh + (long long)btn * LL * HH;
    for (int h = tid; h < HH; h += 256) {
        float acc[EE] = {};
#pragma unroll 4
        for (int l = 0; l < LL; l++) {
            float v = nb[(long long)l * HH + h];
#pragma unroll
            for (int e = 0; e < EE; e++) acc[e] += sl[e][l] * v;
        }
        float p = 0.f;
#pragma unroll
        for (int e = 0; e < EE; e++) {
            msgs[((long long)btn * EE + e) * HH + h] = acc[e];
            p += acc[e];
        }
        pooled[(long long)btn * HH + h] = p * (1.f / EE);
    }
}

// ---------------- attn-attr score -------------------------------------------
__global__ void score_kernel(const float* __restrict__ wf, const float* __restrict__ wp,
                             const float* __restrict__ Wa, const float* __restrict__ ba,
                             const float* __restrict__ dists, const float* __restrict__ wb,
                             const float* __restrict__ bb, float* __restrict__ score)
{
    int btn = blockIdx.x;
    int bt = btn / NN;
    int tid = threadIdx.x;
    float t;
    if (tid < AA) t = wf[(long long)bt * AA + tid] * Wa[tid];
    else          t = wp[(long long)btn * AA + (tid - AA)] * Wa[tid];

    __shared__ float red[256];
    red[tid] = t;
    __syncthreads();
    for (int s = 128; s > 0; s >>= 1) {
        if (tid < s) red[tid] += red[tid + s];
        __syncthreads();
    }
    if (tid == 0) {
        float xv = red[0] + ba[0];
        xv = (xv > 0.f) ? xv : 0.01f * xv;
        xv += dists[btn] * wb[0] + bb[0];
        score[btn] = 1.f / (1.f + __expf(-xv));
    }
}

// ---------------- scatter-add gated messages into entity spans --------------
__global__ void scatter_kernel(const float* __restrict__ score,
                               const float* __restrict__ msgs,
                               const int* __restrict__ spans,
                               float* __restrict__ x)
{
    int bte = blockIdx.x;
    int e = bte % EE;
    int bt = bte / EE;
    int b = bt / TT;
    int pos = spans[bt] + e;

    __shared__ float sc[NN];
    if (threadIdx.x < NN) sc[threadIdx.x] = score[(long long)bt * NN + threadIdx.x];
    __syncthreads();

    for (int h = threadIdx.x; h < HH; h += blockDim.x) {
        float d = 0.f;
        for (int n = 0; n < NN; n++)
            d += sc[n] * msgs[(((long long)bt * NN + n) * EE + e) * HH + h];
        atomicAdd(&x[((long long)b * SS + pos) * HH + h], d);
    }
}

// ---------------- row softmax over 512 cols ---------------------------------
__global__ void softmax512(float* __restrict__ X)
{
    long long row = blockIdx.x;
    float* p = X + row * SS;
    int tid = threadIdx.x;
    float v0 = p[tid], v1 = p[tid + 256];

    __shared__ float red[256];
    red[tid] = fmaxf(v0, v1);
    __syncthreads();
    for (int s = 128; s > 0; s >>= 1) {
        if (tid < s) red[tid] = fmaxf(red[tid], red[tid + s]);
        __syncthreads();
    }
    float m = red[0];
    __syncthreads();

    float e0 = __expf(v0 - m), e1 = __expf(v1 - m);
    red[tid] = e0 + e1;
    __syncthreads();
    for (int s = 128; s > 0; s >>= 1) {
        if (tid < s) red[tid] += red[tid + s];
        __syncthreads();
    }
    float inv = 1.f / red[0];
    p[tid] = e0 * inv;
    p[tid + 256] = e1 * inv;
}

// ---------------- host orchestration ----------------------------------------
static void launch_sgemm(const float* A, const float* Bw, const float* bias, float* C,
                         int M, int N, int K)
{
    dim3 g((N + 63) / 64, (M + 63) / 64, 1);
    sgemm_bias<<<g, 256>>>(A, Bw, bias, C, M, N, K, 0, 0, 0);
}

static void launch_mmf(const float* A, const __nv_bfloat16* Bh, const __nv_bfloat16* Bl,
                       const float* bias, float* C,
                       int M, int N, int K, float alpha, int batch,
                       long long sA, long long sB, long long sC)
{
    dim3 g(N / 128, M / 128, batch);
    mmf<<<g, 256, MM_SMEM_BYTES>>>(A, Bh, Bl, bias, C, M, N, K, alpha, sA, sB, sC);
}

extern "C" void kernel_launch(void* const* d_in, const int* in_sizes, int n_in,
                              void* d_out, int out_size)
{
    const float* xs    = (const float*)d_in[0];
    const float* neigh = (const float*)d_in[1];
    const float* dists = (const float*)d_in[2];
    const int*   spans = (const int*)d_in[3];
    const float* Wq = (const float*)d_in[4];
    const float* bq = (const float*)d_in[5];
    const float* Wk = (const float*)d_in[6];
    const float* bk = (const float*)d_in[7];
    const float* Wv = (const float*)d_in[8];
    const float* bv = (const float*)d_in[9];
    const float* Ww = (const float*)d_in[10];
    const float* bw = (const float*)d_in[11];
    const float* Wa = (const float*)d_in[12];
    const float* ba = (const float*)d_in[13];
    const float* wb = (const float*)d_in[14];
    const float* bb = (const float*)d_in[15];
    float* out = (float*)d_out;

    cudaFuncSetAttribute(mmf, cudaFuncAttributeMaxDynamicSharedMemorySize, MM_SMEM_BYTES);

    float *p_efea, *p_feas, *p_q, *p_k, *p_msgs, *p_pooled, *p_wf, *p_wp, *p_score;
    float *p_x, *p_q2, *p_k2, *p_v2, *p_s2;
    cudaGetSymbolAddress((void**)&p_efea,   g_efea);
    cudaGetSymbolAddress((void**)&p_feas,   g_feas);
    cudaGetSymbolAddress((void**)&p_q,      g_q);
    cudaGetSymbolAddress((void**)&p_k,      g_k);
    cudaGetSymbolAddress((void**)&p_msgs,   g_msgs);
    cudaGetSymbolAddress((void**)&p_pooled, g_pooled);
    cudaGetSymbolAddress((void**)&p_wf,     g_wf);
    cudaGetSymbolAddress((void**)&p_wp,     g_wp);
    cudaGetSymbolAddress((void**)&p_score,  g_score);
    cudaGetSymbolAddress((void**)&p_x,      g_x);
    cudaGetSymbolAddress((void**)&p_q2,     g_q2);
    cudaGetSymbolAddress((void**)&p_k2,     g_k2);
    cudaGetSymbolAddress((void**)&p_v2,     g_v2);
    cudaGetSymbolAddress((void**)&p_s2,     g_s2);

    __nv_bfloat16 *k2h, *k2l, *vth, *vtl;
    __nv_bfloat16 *WkTh, *WkTl, *WqTh, *WqTl, *WvTh, *WvTl;
    cudaGetSymbolAddress((void**)&k2h,  g_k2h);
    cudaGetSymbolAddress((void**)&k2l,  g_k2l);
    cudaGetSymbolAddress((void**)&vth,  g_vth);
    cudaGetSymbolAddress((void**)&vtl,  g_vtl);
    cudaGetSymbolAddress((void**)&WkTh, g_WkTh);
    cudaGetSymbolAddress((void**)&WkTl, g_WkTl);
    cudaGetSymbolAddress((void**)&WqTh, g_WqTh);
    cudaGetSymbolAddress((void**)&WqTl, g_WqTl);
    cudaGetSymbolAddress((void**)&WvTh, g_WvTh);
    cudaGetSymbolAddress((void**)&WvTl, g_WvTl);

    // --- weight transposes+splits (tiny): W[H,N] -> W^T[N,H] hi/lo ---
    {
        dim3 g8(32, 8);
        transpose_split<<<dim3(DD / 32, HH / 32, 1), g8>>>(Wk, WkTh, WkTl, HH, DD, 0, 0);
        transpose_split<<<dim3(DD / 32, HH / 32, 1), g8>>>(Wq, WqTh, WqTl, HH, DD, 0, 0);
        transpose_split<<<dim3(HH / 32, HH / 32, 1), g8>>>(Wv, WvTh, WvTl, HH, HH, 0, 0);
    }

    // 1) gather spans + feas
    gather_kernel<<<BB * TT, 256>>>(xs, spans, p_efea, p_feas);

    // 2) q = e_fea @ Wq + bq  (small, fp32)
    launch_sgemm(p_efea, Wq, bq, p_q, BB * TT * EE, DD, HH);

    // 3) k = neigh @ Wk + bk  (fused fp32->bf16x3, A = neigh directly)
    launch_mmf(neigh, WkTh, WkTl, bk, p_k,
               BB * TT * NN * LL, DD, HH, 1.f, 1, 0, 0, 0);

    // 4) per-neighbor SDPA -> msgs, pooled
    sdpa_kernel<<<BB * TT * NN, 256>>>(p_q, p_k, neigh, p_msgs, p_pooled);

    // 5) wf, wp (small/medium, fp32)
    launch_sgemm(p_feas, Ww, bw, p_wf, BB * TT, AA, HH);
    launch_sgemm(p_pooled, Ww, bw, p_wp, BB * TT * NN, AA, HH);

    // 6) sigmoid attn-attr score
    score_kernel<<<BB * TT * NN, 256>>>(p_wf, p_wp, Wa, ba, dists, wb, bb, p_score);

    // 7) x = xs ; x[spans] += sum_n score*msgs
    cudaMemcpyAsync(p_x, xs, (size_t)BB * SS * HH * sizeof(float),
                    cudaMemcpyDeviceToDevice, 0);
    scatter_kernel<<<BB * TT * EE, 256>>>(p_score, p_msgs, spans, p_x);

    // 8) q2/k2/v2 projections (A = x fp32 directly)
    launch_mmf(p_x, WqTh, WqTl, bq, p_q2, BB * SS, DD, HH, 1.f, 1, 0, 0, 0);
    launch_mmf(p_x, WkTh, WkTl, bk, p_k2, BB * SS, DD, HH, 1.f, 1, 0, 0, 0);
    launch_mmf(p_x, WvTh, WvTl, bv, p_v2, BB * SS, HH, HH, 1.f, 1, 0, 0, 0);

    // 9) s2 = q2 @ k2^T * inv_sqrt_d  (A = q2 fp32; B = k2 hi/lo via split)
    {
        long long n4 = (long long)BB * SS * DD / 4;
        split4<<<(int)((n4 + 255) / 256), 256>>>(
            (const float4*)p_k2, (__nv_bfloat162*)k2h, (__nv_bfloat162*)k2l, n4);
    }
    launch_mmf(p_q2, k2h, k2l, nullptr, p_s2, SS, SS, DD, INV_SQRT_D, BB,
               (long long)SS * DD, (long long)SS * DD, (long long)SS * SS);

    // 10) softmax rows (A of out-GEMM stays fp32 -> no P split needed)
    softmax512<<<BB * SS, 256>>>(p_s2);

    // 11) out = P @ v2  (v2^T as [H,S] K-major hi/lo B operand)
    transpose_split<<<dim3(HH / 32, SS / 32, BB), dim3(32, 8)>>>(
        p_v2, vth, vtl, SS, HH, (long long)SS * HH, (long long)HH * SS);
    launch_mmf(p_s2, vth, vtl, nullptr, out, SS, HH, SS, 1.f, BB,
               (long long)SS * SS, (long long)HH * SS, (long long)SS * HH);
}